// round 10
// baseline (speedup 1.0000x reference)
#include <cuda_runtime.h>
#include <stdint.h>

// out[s] = in[0] ^ ... ^ in[s], [4096, 8192], scan verified byte-exact (R7).
// NEW THEORY: checker reads d_out as FLOAT32. Int 0/1 words are denormals
// (~0.0f) -> rel_err == 1.000000 exactly, every round. Fix: convert the
// scanned 0/1 ints to 0.0f/1.0f on the final store. Integer XOR math intact.
// Pipeline: 3-pass, capture-clean, write-once scratch (concurrency-safe).

#define LANES   128
#define GRPS    2
#define THREADS (LANES * GRPS)      // 256
#define VPT     8
#define CHUNK   (GRPS * VPT)        // 16 rows per chunk

#define S_ROWS  4096
#define B_COLS  8192
#define ROW4    (B_COLS / 4)        // 2048 int4 per row
#define NCOL4   ROW4
#define NCHUNK  (S_ROWS / CHUNK)    // 256
#define BSEG    8

__device__ int4 g_part[(size_t)NCHUNK * NCOL4];   // chunk aggregates   (8 MB)
__device__ int4 g_pref[(size_t)NCHUNK * NCOL4];   // exclusive prefixes (8 MB)

__device__ __forceinline__ int4 x4(int4 a, int4 b) {
    a.x ^= b.x; a.y ^= b.y; a.z ^= b.z; a.w ^= b.w; return a;
}

// ---- Pass A: per-(chunk, col) aggregate of 16 rows -> g_part ----
__global__ __launch_bounds__(THREADS)
void pass_a(const int4* __restrict__ in) {
    __shared__ int4 sh[GRPS][LANES];
    const int lane  = threadIdx.x & (LANES - 1);
    const int grp   = threadIdx.x >> 7;
    const int col   = blockIdx.x * LANES + lane;
    const int chunk = blockIdx.y;
    const long r0   = (long)chunk * CHUNK + grp * VPT;

    int4 a = __ldcs(&in[r0 * ROW4 + col]);
#pragma unroll
    for (int i = 1; i < VPT; i++)
        a = x4(a, __ldcs(&in[(r0 + i) * ROW4 + col]));

    sh[grp][lane] = a;
    __syncthreads();
    if (grp == 0)
        g_part[(size_t)chunk * NCOL4 + col] = x4(sh[0][lane], sh[1][lane]);
}

// ---- Pass B: exclusive XOR scan over chunks, g_part -> g_pref (write-once) ----
__global__ __launch_bounds__(LANES * BSEG)
void pass_b() {
    __shared__ int4 sh[BSEG][LANES];
    const int lane = threadIdx.x & (LANES - 1);
    const int seg  = threadIdx.x >> 7;            // 0..7
    const int col  = blockIdx.x * LANES + lane;
    const int L    = NCHUNK / BSEG;               // 32
    const int c0   = seg * L;

    int4 p = make_int4(0, 0, 0, 0);
    for (int c = c0; c < c0 + L; c++)
        p = x4(p, g_part[(size_t)c * NCOL4 + col]);
    sh[seg][lane] = p;
    __syncthreads();

    int4 exc = make_int4(0, 0, 0, 0);
    for (int s = 0; s < seg; s++) exc = x4(exc, sh[s][lane]);

    for (int c = c0; c < c0 + L; c++) {
        const size_t idx = (size_t)c * NCOL4 + col;
        g_pref[idx] = exc;                        // separate array: no mutation
        exc = x4(exc, g_part[idx]);
    }
}

// ---- Pass C: re-read input, apply prefixes, emit FLOAT32 output ----
__global__ __launch_bounds__(THREADS)
void pass_c(const int4* __restrict__ in, float4* __restrict__ out) {
    __shared__ int4 sh[GRPS][LANES];
    const int lane  = threadIdx.x & (LANES - 1);
    const int grp   = threadIdx.x >> 7;
    const int col   = blockIdx.x * LANES + lane;
    const int chunk = blockIdx.y;
    const long r0   = (long)chunk * CHUNK + grp * VPT;

    int4 v[VPT];
#pragma unroll
    for (int i = 0; i < VPT; i++)
        v[i] = __ldcs(&in[(r0 + i) * ROW4 + col]);
#pragma unroll
    for (int i = 1; i < VPT; i++) v[i] = x4(v[i], v[i - 1]);

    sh[grp][lane] = v[VPT - 1];
    __syncthreads();

    int4 gexc = make_int4(0, 0, 0, 0);
    if (grp > 0) gexc = sh[0][lane];

    const int4 pre = x4(g_pref[(size_t)chunk * NCOL4 + col], gexc);

#pragma unroll
    for (int i = 0; i < VPT; i++) {
        const int4 r = x4(v[i], pre);
        float4 f;
        f.x = (float)r.x; f.y = (float)r.y; f.z = (float)r.z; f.w = (float)r.w;
        __stcs(&out[(r0 + i) * ROW4 + col], f);
    }
}

extern "C" void kernel_launch(void* const* d_in, const int* in_sizes, int n_in,
                              void* d_out, int out_size) {
    const int4* in  = (const int4*)d_in[0];
    float4*     out = (float4*)d_out;

    dim3 grid(NCOL4 / LANES, NCHUNK);   // (16, 256)
    pass_a<<<grid, THREADS>>>(in);
    pass_b<<<NCOL4 / LANES, LANES * BSEG>>>();
    pass_c<<<grid, THREADS>>>(in, out);
}

// round 11
// speedup vs baseline: 1.2184x; 1.2184x over previous
#include <cuda_runtime.h>
#include <stdint.h>

// out[s] = float(in[0] ^ ... ^ in[s]), in: [4096, 8192] int32 0/1 row-major,
// out: float32 same shape (dtype confirmed R10).
//
// Single-pass decoupled-lookback XOR scan: 1 input read + 1 output write
// (~264 MB total vs 400 MB for the 3-pass R10 kernel).
//  - ticket dispatch: chunk c's owner acquires its ticket after chunk c-1's
//    owner is already resident -> lookback spin cannot deadlock.
//  - per-(tile,chunk,lane) flags; the SAME thread that writes the 16B value
//    publishes with st.release.gpu; readers ld.acquire.gpu then load data.
//  - epoch encoding: g_ticket never resets; epoch = ticket/NBLOCKS; ready
//    flag values are 2e+1 (aggregate) / 2e+2 (inclusive). Stale flags from
//    earlier launches/replays are strictly smaller -> "not ready".

#define SEQ      4096
#define COLS_I32 8192
#define ROW_I4   (COLS_I32 / 4)          // 2048 int4 per row

#define NTILE    16                      // column tiles
#define LANES    128                     // int4 lanes per tile (2KB/row/block)
#define GRPS     4                       // row groups per block
#define VPT      8                       // rows per thread
#define ROWS_PER_CHUNK (GRPS * VPT)      // 32
#define NCHUNK   (SEQ / ROWS_PER_CHUNK)  // 128
#define THREADS  (LANES * GRPS)          // 512
#define NBLOCKS  (NTILE * NCHUNK)        // 2048 = 2^11

__device__ int4         g_agg[(size_t)NTILE * NCHUNK * LANES];   // 4 MB
__device__ int4         g_inc[(size_t)NTILE * NCHUNK * LANES];   // 4 MB
__device__ int          g_flags[NTILE * NCHUNK * LANES];         // 1 MB
__device__ unsigned int g_ticket;                                // never reset

__device__ __forceinline__ int4 x4(int4 a, int4 b) {
    a.x ^= b.x; a.y ^= b.y; a.z ^= b.z; a.w ^= b.w; return a;
}
__device__ __forceinline__ int ld_acq(const int* p) {
    int v;
    asm volatile("ld.acquire.gpu.global.b32 %0, [%1];" : "=r"(v) : "l"(p) : "memory");
    return v;
}
__device__ __forceinline__ void st_rel(int* p, int v) {
    asm volatile("st.release.gpu.global.b32 [%0], %1;" :: "l"(p), "r"(v) : "memory");
}

__global__ __launch_bounds__(THREADS, 2)
void xorscan_kernel(const int4* __restrict__ in, float4* __restrict__ out) {
    __shared__ unsigned int sh_ticket;
    __shared__ int4 sh_agg[GRPS][LANES];   // 8 KB

    const int tid = threadIdx.x;
    if (tid == 0) sh_ticket = atomicAdd(&g_ticket, 1u);
    __syncthreads();
    const unsigned int ticket = sh_ticket;
    const unsigned int lt     = ticket & (NBLOCKS - 1);
    const int epoch2 = (int)((ticket >> 11) * 2u);       // 2*epoch
    const int tile   = lt & (NTILE - 1);
    const int chunk  = (int)(lt >> 4);                   // NTILE = 16

    const int lane = tid & (LANES - 1);
    const int grp  = tid >> 7;                           // LANES = 128

    const long row0 = (long)chunk * ROWS_PER_CHUNK + (long)grp * VPT;
    const long base = row0 * ROW_I4 + (long)tile * LANES + lane;

    // ---- load + thread-local inclusive XOR scan ----
    int4 v[VPT];
#pragma unroll
    for (int i = 0; i < VPT; i++) v[i] = __ldcs(&in[base + (long)i * ROW_I4]);
#pragma unroll
    for (int i = 1; i < VPT; i++) v[i] = x4(v[i], v[i - 1]);

    // ---- cross-group combine via smem ----
    sh_agg[grp][lane] = v[VPT - 1];
    __syncthreads();

    int4 gexc = make_int4(0, 0, 0, 0);   // XOR of group aggregates below mine
    int4 bagg = make_int4(0, 0, 0, 0);   // full block aggregate for my lane
#pragma unroll
    for (int g = 0; g < GRPS; g++) {
        int4 a = sh_agg[g][lane];
        if (g < grp) gexc = x4(gexc, a);
        bagg = x4(bagg, a);
    }

    const size_t lidx = (size_t)(tile * NCHUNK + chunk) * LANES + lane;

    // ---- publish per-lane aggregate early (same-thread release) ----
    if (chunk > 0 && grp == 0) {
        g_agg[lidx] = bagg;
        st_rel(&g_flags[lidx], epoch2 + 1);
    }

    // ---- decoupled lookback (per-thread independent, per-lane data) ----
    int4 exc = make_int4(0, 0, 0, 0);
    if (chunk > 0) {
        int look = chunk - 1;
        while (true) {
            const size_t pidx = (size_t)(tile * NCHUNK + look) * LANES + lane;
            int s;
            do { s = ld_acq(&g_flags[pidx]); } while (s <= epoch2);
            if (s == epoch2 + 2) {                    // inclusive available
                exc = x4(exc, __ldcg(&g_inc[pidx]));
                break;
            }
            exc = x4(exc, __ldcg(&g_agg[pidx]));      // aggregate, keep walking
            look--;
        }
    }

    // ---- publish per-lane inclusive prefix ----
    if (grp == 0) {
        g_inc[lidx] = x4(exc, bagg);
        st_rel(&g_flags[lidx], epoch2 + 2);
    }

    // ---- apply prefix, convert to float32, stream out ----
    const int4 pre = x4(exc, gexc);
#pragma unroll
    for (int i = 0; i < VPT; i++) {
        const int4 r = x4(v[i], pre);
        float4 f;
        f.x = (float)r.x; f.y = (float)r.y; f.z = (float)r.z; f.w = (float)r.w;
        __stcs(&out[base + (long)i * ROW_I4], f);
    }
}

extern "C" void kernel_launch(void* const* d_in, const int* in_sizes, int n_in,
                              void* d_out, int out_size) {
    const int4* in  = (const int4*)d_in[0];
    float4*     out = (float4*)d_out;
    xorscan_kernel<<<NBLOCKS, THREADS>>>(in, out);
}

// round 12
// speedup vs baseline: 1.3681x; 1.1229x over previous
#include <cuda_runtime.h>
#include <stdint.h>

// out[s] = float(in[0] ^ ... ^ in[s]), in: [4096, 8192] int32 0/1, out float32.
// Single-pass decoupled-lookback XOR scan. R12 reshape:
//  - NTILE=64 x LANES=32 (warp-wide tiles, 512B/row coalesced)
//  - 128 rows/chunk -> NCHUNK=32 (lookback chains 4x shorter than R11)
//  - only group 0 performs lookback; exc broadcast via smem (16x less spin)
//  - int->float via IMAD bit trick (values are 0/1)

#define SEQ      4096
#define COLS_I32 8192
#define ROW_I4   (COLS_I32 / 4)          // 2048 int4 per row

#define NTILE    64                      // column tiles
#define LANES    32                      // int4 lanes per tile (one warp)
#define GRPS     16                      // row groups (warps) per block
#define VPT      8                       // rows per thread
#define ROWS_PER_CHUNK (GRPS * VPT)      // 128
#define NCHUNK   (SEQ / ROWS_PER_CHUNK)  // 32
#define THREADS  (LANES * GRPS)          // 512
#define NBLOCKS  (NTILE * NCHUNK)        // 2048 = 2^11

__device__ int4         g_agg[(size_t)NTILE * NCHUNK * LANES];   // 1 MB
__device__ int4         g_inc[(size_t)NTILE * NCHUNK * LANES];   // 1 MB
__device__ int          g_flags[NTILE * NCHUNK * LANES];         // 256 KB
__device__ unsigned int g_ticket;                                // never reset

__device__ __forceinline__ int4 x4(int4 a, int4 b) {
    a.x ^= b.x; a.y ^= b.y; a.z ^= b.z; a.w ^= b.w; return a;
}
__device__ __forceinline__ int ld_acq(const int* p) {
    int v;
    asm volatile("ld.acquire.gpu.global.b32 %0, [%1];" : "=r"(v) : "l"(p) : "memory");
    return v;
}
__device__ __forceinline__ void st_rel(int* p, int v) {
    asm volatile("st.release.gpu.global.b32 [%0], %1;" :: "l"(p), "r"(v) : "memory");
}
__device__ __forceinline__ float4 tofloat01(int4 r) {
    float4 f;
    f.x = __int_as_float(r.x * 0x3f800000);
    f.y = __int_as_float(r.y * 0x3f800000);
    f.z = __int_as_float(r.z * 0x3f800000);
    f.w = __int_as_float(r.w * 0x3f800000);
    return f;
}

__global__ __launch_bounds__(THREADS, 2)
void xorscan_kernel(const int4* __restrict__ in, float4* __restrict__ out) {
    __shared__ unsigned int sh_ticket;
    __shared__ int4 sh_agg[GRPS][LANES];   // 8 KB
    __shared__ int4 sh_exc[LANES];         // 512 B

    const int tid = threadIdx.x;
    if (tid == 0) sh_ticket = atomicAdd(&g_ticket, 1u);
    __syncthreads();
    const unsigned int ticket = sh_ticket;
    const unsigned int lt     = ticket & (NBLOCKS - 1);
    const int epoch2 = (int)((ticket >> 11) * 2u);       // 2*epoch
    const int tile   = (int)(lt & (NTILE - 1));          // fills all tiles first
    const int chunk  = (int)(lt >> 6);                   // NTILE = 64

    const int lane = tid & (LANES - 1);
    const int grp  = tid >> 5;                           // warp id

    const long row0 = (long)chunk * ROWS_PER_CHUNK + (long)grp * VPT;
    const long base = row0 * ROW_I4 + (long)tile * LANES + lane;

    // ---- load + thread-local inclusive XOR scan ----
    int4 v[VPT];
#pragma unroll
    for (int i = 0; i < VPT; i++) v[i] = __ldcs(&in[base + (long)i * ROW_I4]);
#pragma unroll
    for (int i = 1; i < VPT; i++) v[i] = x4(v[i], v[i - 1]);

    // ---- cross-group combine via smem ----
    sh_agg[grp][lane] = v[VPT - 1];
    __syncthreads();

    int4 gexc = make_int4(0, 0, 0, 0);   // XOR of group aggregates below mine
    int4 bagg = make_int4(0, 0, 0, 0);   // full block aggregate for my lane
#pragma unroll
    for (int g = 0; g < GRPS; g++) {
        int4 a = sh_agg[g][lane];
        if (g < grp) gexc = x4(gexc, a);
        bagg = x4(bagg, a);
    }

    const size_t lidx = (size_t)(tile * NCHUNK + chunk) * LANES + lane;

    // ---- group 0: publish aggregate, lookback, publish inclusive ----
    if (grp == 0) {
        if (chunk > 0) {
            g_agg[lidx] = bagg;
            st_rel(&g_flags[lidx], epoch2 + 1);
        }
        int4 exc = make_int4(0, 0, 0, 0);
        if (chunk > 0) {
            int look = chunk - 1;
            while (true) {
                const size_t pidx = (size_t)(tile * NCHUNK + look) * LANES + lane;
                int s;
                do { s = ld_acq(&g_flags[pidx]); } while (s <= epoch2);
                if (s == epoch2 + 2) {                    // inclusive available
                    exc = x4(exc, __ldcg(&g_inc[pidx]));
                    break;
                }
                exc = x4(exc, __ldcg(&g_agg[pidx]));      // aggregate, walk on
                look--;
            }
        }
        g_inc[lidx] = x4(exc, bagg);
        st_rel(&g_flags[lidx], epoch2 + 2);
        sh_exc[lane] = exc;
    }
    __syncthreads();

    // ---- apply prefix, convert to float, stream out ----
    const int4 pre = x4(sh_exc[lane], gexc);
#pragma unroll
    for (int i = 0; i < VPT; i++) {
        __stcs(&out[base + (long)i * ROW_I4], tofloat01(x4(v[i], pre)));
    }
}

extern "C" void kernel_launch(void* const* d_in, const int* in_sizes, int n_in,
                              void* d_out, int out_size) {
    const int4* in  = (const int4*)d_in[0];
    float4*     out = (float4*)d_out;
    xorscan_kernel<<<NBLOCKS, THREADS>>>(in, out);
}